// round 11
// baseline (speedup 1.0000x reference)
#include <cuda_runtime.h>

#define N_NODES  100000
#define N_EDGES  1600000
#define HID      128
#define IN_F     10
#define OUT_F    101
#define N_GRAPHS 64
#define NBLK     148
#define NTHR     256
#define NT       (NBLK * NTHR)

// ---------------- device state (used only WITHIN one launch) -------------------
__device__ float d_h0[(size_t)N_NODES * HID];
__device__ float d_h1[(size_t)N_NODES * HID];
__device__ int   d_deg[N_NODES];
__device__ float d_dis[N_NODES];
__device__ float d_gsum[N_GRAPHS * HID];
__device__ int   d_gcnt[N_GRAPHS];
__device__ int   d_ei64, d_b64;
__device__ int   g_arrive;            // monotonic grid-barrier ticket

// int32/int64-agnostic index read (LE lo word)
__device__ __forceinline__ int ld_idx(const int* __restrict__ p, int i, int is64) {
    return is64 ? __ldg(p + 2 * (size_t)i) : __ldg(p + i);
}

// Software grid barrier: all NBLK blocks are co-resident (grid == #SMs), so
// spinning is deadlock-free. __threadfence (gpu scope) both publishes our
// writes and invalidates L1 (CCTL.IVALL on sm_103a), making post-barrier
// plain loads coherent. Monotonic ticket => no reset, replay-safe.
__device__ __forceinline__ void gbar() {
    __threadfence();
    __syncthreads();
    if (threadIdx.x == 0) {
        int t = atomicAdd(&g_arrive, 1);
        int target = (t / NBLK + 1) * NBLK;
        while (atomicAdd(&g_arrive, 0) < target) __nanosleep(64);
    }
    __syncthreads();
    __threadfence();
}

__global__ void __launch_bounds__(NTHR)
k_uber(const float* __restrict__ x, const int* __restrict__ ei,
       const int* __restrict__ batch,
       const float* __restrict__ W1, const float* __restrict__ b1,
       const float* __restrict__ W2, const float* __restrict__ b2,
       const float* __restrict__ W3, const float* __restrict__ b3,
       const float* __restrict__ Wl, const float* __restrict__ bl,
       float* __restrict__ out) {
    const int gt = blockIdx.x * NTHR + threadIdx.x;

    // ---- S0: init deg/gsum/gcnt + dtype detection (block 0) ----
    for (int i = gt; i < N_NODES; i += NT) d_deg[i] = 1;       // self-loop
    for (int i = gt; i < N_GRAPHS * HID; i += NT) d_gsum[i] = 0.f;
    for (int i = gt; i < N_GRAPHS; i += NT) d_gcnt[i] = 0;
    if (blockIdx.x == 0) {
        __shared__ int s_ei, s_b;
        if (threadIdx.x == 0) { s_ei = 1; s_b = 1; }
        __syncthreads();
        for (int k = 0; k < 8; k++) {
            int t = threadIdx.x * 8 + k;                       // 0..2047
            if (__ldg(ei + ((t * (2 * N_EDGES / 2048)) | 1)) != 0) s_ei = 0;
            if (__ldg(batch + ((t * (N_NODES / 2048)) | 1)) != 0) s_b = 0;
        }
        __syncthreads();
        if (threadIdx.x == 0) { d_ei64 = s_ei; d_b64 = s_b; }
    }
    gbar();

    // ---- S1: degree count ----
    {
        int f = d_ei64;
        for (int e = gt; e < N_EDGES; e += NT)
            atomicAdd(&d_deg[ld_idx(ei, N_EDGES + e, f)], 1);
    }
    gbar();

    // ---- S2: dis = rsqrt(deg) ----
    for (int i = gt; i < N_NODES; i += NT)
        d_dis[i] = rsqrtf((float)d_deg[i]);
    gbar();

    // ---- helper lambdas over stages ----
    const int ef = d_ei64;   // stable after S0 barrier

    // ---- S3: L1 transform: h0 = x @ W1 ----
    for (int i = gt; i < N_NODES * HID; i += NT) {
        int n = i >> 7, c = i & 127;
        const float* xr = x + (size_t)n * IN_F;
        float acc = 0.f;
        #pragma unroll
        for (int k = 0; k < IN_F; k++)
            acc += __ldg(xr + k) * __ldg(W1 + k * HID + c);
        d_h0[i] = acc;
    }
    gbar();

    // ================= per-layer macro-ish blocks =================
    #define AGG_INIT(BIAS)                                              \
        for (int i = gt; i < N_NODES * HID; i += NT) {                  \
            int n = i >> 7, c = i & 127;                                \
            float dv = d_dis[n];                                        \
            d_h1[i] = dv * dv * d_h0[i] + __ldg((BIAS) + c);            \
        }

    #define SCATTER()                                                   \
        {                                                               \
            int lane = threadIdx.x & 31;                                \
            int w0 = gt >> 5, nw = NT >> 5;                             \
            for (int e = w0; e < N_EDGES; e += nw) {                    \
                int s = ld_idx(ei, e, ef);                              \
                int d = ld_idx(ei, N_EDGES + e, ef);                    \
                float w = d_dis[s] * d_dis[d];                          \
                const float* src = d_h0 + (size_t)s * HID;              \
                float*       dst = d_h1 + (size_t)d * HID;              \
                _Pragma("unroll")                                       \
                for (int j = 0; j < 4; j++)                             \
                    atomicAdd(dst + lane + 32 * j,                      \
                              w * src[lane + 32 * j]);                  \
            }                                                           \
        }

    #define XFORM128(W)  /* h0 = relu(h1) @ W */                        \
        for (int i = gt; i < N_NODES * HID; i += NT) {                  \
            int n = i >> 7, c = i & 127;                                \
            const float* hr = d_h1 + (size_t)n * HID;                   \
            float acc = 0.f;                                            \
            _Pragma("unroll 8")                                         \
            for (int k = 0; k < HID; k++)                               \
                acc += fmaxf(hr[k], 0.f) * __ldg((W) + k * HID + c);    \
            d_h0[i] = acc;                                              \
        }

    // ---- S4-S5: L1 aggregate ----
    AGG_INIT(b1); gbar();
    SCATTER();    gbar();
    // (relu folded into next xform's reads)

    // ---- S6-S8: layer 2 ----
    XFORM128(W2); gbar();
    AGG_INIT(b2); gbar();
    SCATTER();    gbar();

    // ---- S9-S11: layer 3 (no relu after) ----
    XFORM128(W3); gbar();
    AGG_INIT(b3); gbar();
    SCATTER();    gbar();

    // ---- S12: mean-pool accumulate ----
    {
        int f = d_b64;
        for (int i = gt; i < N_NODES * HID; i += NT) {
            int n = i >> 7, c = i & 127;
            int g = ld_idx(batch, n, f);
            atomicAdd(&d_gsum[g * HID + c], d_h1[i]);
            if (c == 0) atomicAdd(&d_gcnt[g], 1);
        }
    }
    gbar();

    // ---- S13: head: out = pooled @ Wl + bl ----
    for (int i = gt; i < N_GRAPHS * OUT_F; i += NT) {
        int g = i / OUT_F, c = i - g * OUT_F;
        float inv = 1.f / (float)max(d_gcnt[g], 1);
        float acc = __ldg(bl + c);
        #pragma unroll 8
        for (int k = 0; k < HID; k++)
            acc += (d_gsum[g * HID + k] * inv) * __ldg(Wl + k * OUT_F + c);
        out[i] = acc;
    }
}

// ---------------- launch ---------------------------------------------------------
extern "C" void kernel_launch(void* const* d_in, const int* in_sizes, int n_in,
                              void* d_out, int out_size) {
    const float *x = 0, *W1 = 0, *W2 = 0, *W3 = 0, *Wl = 0, *bl = 0;
    const float *bias[3] = {0, 0, 0};
    const int *ei = 0, *batch = 0;
    int nbias = 0, nW = 0;
    for (int i = 0; i < n_in; i++) {
        int sz = in_sizes[i];
        const void* p = d_in[i];
        switch (sz) {
            case N_NODES * IN_F:   x     = (const float*)p;  break;
            case 2 * N_EDGES:      ei    = (const int*)p;    break;
            case N_NODES:          batch = (const int*)p;    break;
            case IN_F * HID:       W1    = (const float*)p;  break;
            case HID * HID:        if (nW == 0) W2 = (const float*)p; else W3 = (const float*)p; nW++; break;
            case HID:              if (nbias < 3) bias[nbias++] = (const float*)p; break;
            case HID * OUT_F:      Wl    = (const float*)p;  break;
            case OUT_F:            bl    = (const float*)p;  break;
            default: break;
        }
    }

    k_uber<<<NBLK, NTHR>>>(x, ei, batch,
                           W1, bias[0], W2, bias[1], W3, bias[2],
                           Wl, bl, (float*)d_out);
}

// round 12
// speedup vs baseline: 11.2309x; 11.2309x over previous
#include <cuda_runtime.h>

#define N_NODES  100000
#define N_EDGES  1600000
#define HID      128
#define IN_F     10
#define OUT_F    101
#define N_GRAPHS 64
#define NTHR     256
#define NSC      ((N_NODES + NTHR - 1) / NTHR)   // 391 scan blocks

// ---------------- device state (single-launch lifetime) ------------------------
__device__ __align__(16) float d_h0[(size_t)N_NODES * HID];
__device__ __align__(16) float d_h1[(size_t)N_NODES * HID];
__device__ int   d_deg[N_NODES];
__device__ float d_dis[N_NODES];
__device__ int   d_rowptr[N_NODES];
__device__ int   d_cursor[N_NODES];
__device__ int   d_bsum[NSC];
__device__ int   d_csr_src[N_EDGES];
__device__ float d_csr_w[N_EDGES];
__device__ float d_gsum[N_GRAPHS * HID];
__device__ int   d_gcnt[N_GRAPHS];
__device__ int   d_ei64, d_b64;
__device__ int   g_arrive;            // monotonic grid-barrier ticket

__device__ __forceinline__ int ld_idx(const int* __restrict__ p, int i, int is64) {
    return is64 ? __ldg(p + 2 * (size_t)i) : __ldg(p + i);
}

// Grid barrier (proven in R11): co-resident grid, monotonic ticket, fences.
__device__ __forceinline__ void gbar() {
    __threadfence();
    __syncthreads();
    if (threadIdx.x == 0) {
        int g = gridDim.x;
        int t = atomicAdd(&g_arrive, 1);
        int target = (t / g + 1) * g;
        while (*((volatile int*)&g_arrive) < target) __nanosleep(64);
    }
    __syncthreads();
    __threadfence();
}

__global__ void __launch_bounds__(NTHR, 8)
k_uber(const float* __restrict__ x, const int* __restrict__ ei,
       const int* __restrict__ batch,
       const float* __restrict__ W1, const float* __restrict__ b1,
       const float* __restrict__ W2, const float* __restrict__ b2,
       const float* __restrict__ W3, const float* __restrict__ b3,
       const float* __restrict__ Wl, const float* __restrict__ bl,
       float* __restrict__ out) {
    const int NT   = gridDim.x * blockDim.x;
    const int gt   = blockIdx.x * blockDim.x + threadIdx.x;
    const int lane = threadIdx.x & 31;
    const int wid  = gt >> 5;
    const int nw   = NT >> 5;
    __shared__ int sh[512];

    // ---- S0: init + dtype detection ----
    for (int i = gt; i < N_NODES; i += NT) d_deg[i] = 1;        // self-loop
    for (int i = gt; i < N_GRAPHS * HID; i += NT) d_gsum[i] = 0.f;
    for (int i = gt; i < N_GRAPHS; i += NT) d_gcnt[i] = 0;
    if (blockIdx.x == 0) {
        __shared__ int s_ei, s_b;
        if (threadIdx.x == 0) { s_ei = 1; s_b = 1; }
        __syncthreads();
        for (int k = 0; k < 8; k++) {
            int t = threadIdx.x * 8 + k;
            if (__ldg(ei + ((t * (2 * N_EDGES / 2048)) | 1)) != 0) s_ei = 0;
            if (__ldg(batch + ((t * (N_NODES / 2048)) | 1)) != 0) s_b = 0;
        }
        __syncthreads();
        if (threadIdx.x == 0) { d_ei64 = s_ei; d_b64 = s_b; }
    }
    gbar();
    const int ef = d_ei64;
    const int bf = d_b64;

    // ---- S1: degree histogram ----
    for (int e = gt; e < N_EDGES; e += NT)
        atomicAdd(&d_deg[ld_idx(ei, N_EDGES + e, ef)], 1);
    gbar();

    // ---- S2: dis = rsqrt(deg) ----
    for (int i = gt; i < N_NODES; i += NT)
        d_dis[i] = rsqrtf((float)d_deg[i]);
    gbar();

    // ---- S3: scan phase A — per-block inclusive scan of (deg-1) ----
    if (blockIdx.x < NSC) {
        int i = blockIdx.x * NTHR + threadIdx.x;
        int c = (i < N_NODES) ? (d_deg[i] - 1) : 0;
        sh[threadIdx.x] = c;
        __syncthreads();
        #pragma unroll
        for (int off = 1; off < NTHR; off <<= 1) {
            int t = (threadIdx.x >= off) ? sh[threadIdx.x - off] : 0;
            __syncthreads();
            sh[threadIdx.x] += t;
            __syncthreads();
        }
        if (i < N_NODES) d_rowptr[i] = sh[threadIdx.x] - c;   // exclusive, local
        if (threadIdx.x == NTHR - 1) d_bsum[blockIdx.x] = sh[NTHR - 1];
    }
    gbar();

    // ---- S4: scan phase B — block 0 scans the 391 block sums ----
    if (blockIdx.x == 0) {
        for (int t = threadIdx.x; t < NSC; t += NTHR) sh[t] = d_bsum[t];
        __syncthreads();
        if (threadIdx.x == 0) {
            int run = 0;
            for (int b = 0; b < NSC; b++) { int t = sh[b]; sh[b] = run; run += t; }
        }
        __syncthreads();
        for (int t = threadIdx.x; t < NSC; t += NTHR) d_bsum[t] = sh[t];
    }
    gbar();

    // ---- S5: scan phase C — add block offsets; init cursors ----
    for (int i = gt; i < N_NODES; i += NT) {
        int v = d_rowptr[i] + d_bsum[i / NTHR];
        d_rowptr[i] = v;
        d_cursor[i] = v;
    }
    gbar();

    // ---- S6: CSR fill ----
    for (int e = gt; e < N_EDGES; e += NT) {
        int s = ld_idx(ei, e, ef);
        int d = ld_idx(ei, N_EDGES + e, ef);
        int pos = atomicAdd(&d_cursor[d], 1);
        d_csr_src[pos] = s;
        d_csr_w[pos]   = d_dis[s] * d_dis[d];
    }
    gbar();

    // ---- S7: L1 transform: h0 = x @ W1 (scalar; K=10) ----
    for (int i = gt; i < N_NODES * HID; i += NT) {
        int n = i >> 7, c = i & 127;
        const float* xr = x + (size_t)n * IN_F;
        float acc = 0.f;
        #pragma unroll
        for (int k = 0; k < IN_F; k++)
            acc += __ldg(xr + k) * __ldg(W1 + k * HID + c);
        d_h0[i] = acc;
    }
    gbar();

    // ================== phase macros ==================
    // GATHER: h1[n] = selfw*h0[n] + sum_in w*h0[src] + bias  (optional relu)
    #define GATHER(BIAS, RELU)                                               \
        for (int node = wid; node < N_NODES; node += nw) {                   \
            float dv = d_dis[node];                                          \
            float4 h = ((const float4*)(d_h0 + (size_t)node * HID))[lane];   \
            float sw = dv * dv;                                              \
            float4 acc;                                                      \
            acc.x = sw * h.x; acc.y = sw * h.y;                              \
            acc.z = sw * h.z; acc.w = sw * h.w;                              \
            int start = d_rowptr[node];                                      \
            int cnt   = d_deg[node] - 1;                                     \
            for (int j = 0; j < cnt; j++) {                                  \
                int   s = __ldg(d_csr_src + start + j);                      \
                float w = __ldg(d_csr_w + start + j);                        \
                float4 v = ((const float4*)(d_h0 + (size_t)s * HID))[lane];  \
                acc.x += w * v.x; acc.y += w * v.y;                          \
                acc.z += w * v.z; acc.w += w * v.w;                          \
            }                                                                \
            acc.x += __ldg((BIAS) + lane * 4 + 0);                           \
            acc.y += __ldg((BIAS) + lane * 4 + 1);                           \
            acc.z += __ldg((BIAS) + lane * 4 + 2);                           \
            acc.w += __ldg((BIAS) + lane * 4 + 3);                           \
            if (RELU) {                                                      \
                acc.x = fmaxf(acc.x, 0.f); acc.y = fmaxf(acc.y, 0.f);        \
                acc.z = fmaxf(acc.z, 0.f); acc.w = fmaxf(acc.w, 0.f);        \
            }                                                                \
            ((float4*)(d_h1 + (size_t)node * HID))[lane] = acc;              \
        }

    // XFORM: h0 = h1 @ W — warp per 2 nodes, lane holds float4 of 4 cols
    #define XFORM128(W)                                                      \
        for (int p = wid; p < N_NODES / 2; p += nw) {                        \
            const float* r0 = d_h1 + (size_t)(2 * p) * HID;                  \
            const float* r1 = r0 + HID;                                      \
            const float4* Wv = (const float4*)(W);                           \
            float4 a0 = make_float4(0.f, 0.f, 0.f, 0.f), a1 = a0;            \
            _Pragma("unroll 4")                                              \
            for (int k = 0; k < HID; k++) {                                  \
                float v0 = __ldg(r0 + k);                                    \
                float v1 = __ldg(r1 + k);                                    \
                float4 w = __ldg(Wv + k * 32 + lane);                        \
                a0.x += v0 * w.x; a0.y += v0 * w.y;                          \
                a0.z += v0 * w.z; a0.w += v0 * w.w;                          \
                a1.x += v1 * w.x; a1.y += v1 * w.y;                          \
                a1.z += v1 * w.z; a1.w += v1 * w.w;                          \
            }                                                                \
            ((float4*)(d_h0 + (size_t)(2 * p) * HID))[lane] = a0;            \
            ((float4*)(d_h0 + (size_t)(2 * p) * HID + HID))[lane] = a1;      \
        }

    // ---- S8: L1 aggregate (relu) ----
    GATHER(b1, 1); gbar();
    // ---- S9-S10: layer 2 ----
    XFORM128(W2); gbar();
    GATHER(b2, 1); gbar();
    // ---- S11-S12: layer 3 (no relu) ----
    XFORM128(W3); gbar();
    GATHER(b3, 0); gbar();

    // ---- S13: mean-pool accumulate ----
    for (int i = gt; i < N_NODES * HID; i += NT) {
        int n = i >> 7, c = i & 127;
        int g = ld_idx(batch, n, bf);
        atomicAdd(&d_gsum[g * HID + c], d_h1[i]);
        if (c == 0) atomicAdd(&d_gcnt[g], 1);
    }
    gbar();

    // ---- S14: head ----
    for (int i = gt; i < N_GRAPHS * OUT_F; i += NT) {
        int g = i / OUT_F, c = i - g * OUT_F;
        float inv = 1.f / (float)max(d_gcnt[g], 1);
        float acc = __ldg(bl + c);
        #pragma unroll 8
        for (int k = 0; k < HID; k++)
            acc += (d_gsum[g * HID + k] * inv) * __ldg(Wl + k * OUT_F + c);
        out[i] = acc;
    }
}

// ---------------- launch ---------------------------------------------------------
extern "C" void kernel_launch(void* const* d_in, const int* in_sizes, int n_in,
                              void* d_out, int out_size) {
    const float *x = 0, *W1 = 0, *W2 = 0, *W3 = 0, *Wl = 0, *bl = 0;
    const float *bias[3] = {0, 0, 0};
    const int *ei = 0, *batch = 0;
    int nbias = 0, nW = 0;
    for (int i = 0; i < n_in; i++) {
        int sz = in_sizes[i];
        const void* p = d_in[i];
        switch (sz) {
            case N_NODES * IN_F:   x     = (const float*)p;  break;
            case 2 * N_EDGES:      ei    = (const int*)p;    break;
            case N_NODES:          batch = (const int*)p;    break;
            case IN_F * HID:       W1    = (const float*)p;  break;
            case HID * HID:        if (nW == 0) W2 = (const float*)p; else W3 = (const float*)p; nW++; break;
            case HID:              if (nbias < 3) bias[nbias++] = (const float*)p; break;
            case HID * OUT_F:      Wl    = (const float*)p;  break;
            case OUT_F:            bl    = (const float*)p;  break;
            default: break;
        }
    }

    // size the co-resident grid from the occupancy API (no caching; cheap)
    int sm = 148, mb = 1;
    cudaDeviceGetAttribute(&sm, cudaDevAttrMultiProcessorCount, 0);
    cudaOccupancyMaxActiveBlocksPerMultiprocessor(&mb, k_uber, NTHR, 0);
    if (mb < 1) mb = 1;
    if (mb > 8) mb = 8;
    int grid = sm * mb;

    k_uber<<<grid, NTHR>>>(x, ei, batch,
                           W1, bias[0], W2, bias[1], W3, bias[2],
                           Wl, bl, (float*)d_out);
}

// round 13
// speedup vs baseline: 16.9642x; 1.5105x over previous
#include <cuda_runtime.h>

#define N_NODES  100000
#define N_EDGES  1600000
#define HID      128
#define IN_F     10
#define OUT_F    101
#define N_GRAPHS 64
#define NTHR     256
#define NSC      ((N_NODES + NTHR - 1) / NTHR)   // 391 scan blocks

// ---------------- device state (single-launch lifetime) ------------------------
__device__ __align__(16) float d_h0[(size_t)N_NODES * HID];
__device__ __align__(16) float d_h1[(size_t)N_NODES * HID];
__device__ __align__(16) float d_xa[(size_t)N_NODES * IN_F];  // aggregated x
__device__ int   d_deg[N_NODES];
__device__ float d_dis[N_NODES];
__device__ int   d_rowptr[N_NODES];
__device__ int   d_cursor[N_NODES];
__device__ int   d_bsum[NSC];
__device__ int   d_csr_src[N_EDGES];
__device__ float d_gsum[N_GRAPHS * HID];
__device__ int   d_gcnt[N_GRAPHS];
__device__ int   d_ei64, d_b64;
__device__ int   g_arrive;            // monotonic grid-barrier ticket

__device__ __forceinline__ int ld_idx(const int* __restrict__ p, int i, int is64) {
    return is64 ? __ldg(p + 2 * (size_t)i) : __ldg(p + i);
}

// Grid barrier (proven R11/R12): co-resident grid, monotonic ticket, fences.
__device__ __forceinline__ void gbar() {
    __threadfence();
    __syncthreads();
    if (threadIdx.x == 0) {
        int g = gridDim.x;
        int t = atomicAdd(&g_arrive, 1);
        int target = (t / g + 1) * g;
        while (*((volatile int*)&g_arrive) < target) __nanosleep(64);
    }
    __syncthreads();
    __threadfence();
}

__global__ void __launch_bounds__(NTHR, 4)
k_uber(const float* __restrict__ x, const int* __restrict__ ei,
       const int* __restrict__ batch,
       const float* __restrict__ W1, const float* __restrict__ b1,
       const float* __restrict__ W2, const float* __restrict__ b2,
       const float* __restrict__ W3, const float* __restrict__ b3,
       const float* __restrict__ Wl, const float* __restrict__ bl,
       float* __restrict__ out) {
    const int NT   = gridDim.x * blockDim.x;
    const int gt   = blockIdx.x * blockDim.x + threadIdx.x;
    const int lane = threadIdx.x & 31;
    const int wid  = gt >> 5;
    const int nw   = NT >> 5;
    __shared__ int sh[512];

    // ---- P0: init + dtype detection ----
    for (int i = gt; i < N_NODES; i += NT) d_deg[i] = 1;        // self-loop
    for (int i = gt; i < N_GRAPHS * HID; i += NT) d_gsum[i] = 0.f;
    for (int i = gt; i < N_GRAPHS; i += NT) d_gcnt[i] = 0;
    if (blockIdx.x == 0) {
        __shared__ int s_ei, s_b;
        if (threadIdx.x == 0) { s_ei = 1; s_b = 1; }
        __syncthreads();
        for (int k = 0; k < 8; k++) {
            int t = threadIdx.x * 8 + k;
            if (__ldg(ei + ((t * (2 * N_EDGES / 2048)) | 1)) != 0) s_ei = 0;
            if (__ldg(batch + ((t * (N_NODES / 2048)) | 1)) != 0) s_b = 0;
        }
        __syncthreads();
        if (threadIdx.x == 0) { d_ei64 = s_ei; d_b64 = s_b; }
    }
    gbar();
    const int ef = d_ei64;
    const int bf = d_b64;

    // ---- P1: degree histogram ----
    for (int e = gt; e < N_EDGES; e += NT)
        atomicAdd(&d_deg[ld_idx(ei, N_EDGES + e, ef)], 1);
    gbar();

    // ---- P2: dis = rsqrt(deg)  +  scan phase A (both read deg) ----
    for (int i = gt; i < N_NODES; i += NT)
        d_dis[i] = rsqrtf((float)d_deg[i]);
    if (blockIdx.x < NSC) {
        int i = blockIdx.x * NTHR + threadIdx.x;
        int c = (i < N_NODES) ? (d_deg[i] - 1) : 0;
        sh[threadIdx.x] = c;
        __syncthreads();
        #pragma unroll
        for (int off = 1; off < NTHR; off <<= 1) {
            int t = (threadIdx.x >= off) ? sh[threadIdx.x - off] : 0;
            __syncthreads();
            sh[threadIdx.x] += t;
            __syncthreads();
        }
        if (i < N_NODES) d_rowptr[i] = sh[threadIdx.x] - c;   // exclusive, local
        if (threadIdx.x == NTHR - 1) d_bsum[blockIdx.x] = sh[NTHR - 1];
    }
    gbar();

    // ---- P3: scan phase B ----
    if (blockIdx.x == 0) {
        for (int t = threadIdx.x; t < NSC; t += NTHR) sh[t] = d_bsum[t];
        __syncthreads();
        if (threadIdx.x == 0) {
            int run = 0;
            for (int b = 0; b < NSC; b++) { int t = sh[b]; sh[b] = run; run += t; }
        }
        __syncthreads();
        for (int t = threadIdx.x; t < NSC; t += NTHR) d_bsum[t] = sh[t];
    }
    gbar();

    // ---- P4: scan phase C ----
    for (int i = gt; i < N_NODES; i += NT) {
        int v = d_rowptr[i] + d_bsum[i / NTHR];
        d_rowptr[i] = v;
        d_cursor[i] = v;
    }
    gbar();

    // ---- P5: CSR fill (src ids only; weights recomputed in gather) ----
    for (int e = gt; e < N_EDGES; e += NT) {
        int s = ld_idx(ei, e, ef);
        int d = ld_idx(ei, N_EDGES + e, ef);
        d_csr_src[atomicAdd(&d_cursor[d], 1)] = s;
    }
    gbar();

    // ---- P6: gather on RAW x (10-wide):  xa = A_norm * x ----
    for (int i = gt; i < N_NODES * IN_F; i += NT) {
        int n = i / IN_F, c = i - n * IN_F;
        float dv = d_dis[n];
        float acc = dv * dv * __ldg(x + i);
        int st = d_rowptr[n], cnt = d_deg[n] - 1;
        for (int j = 0; j < cnt; j++) {
            int s = __ldg(d_csr_src + st + j);
            acc += __ldg(&d_dis[s]) * dv * __ldg(x + (size_t)s * IN_F + c);
        }
        d_xa[i] = acc;
    }
    gbar();

    // ---- P7: layer-1 transform:  h1 = relu(xa @ W1 + b1) ----
    for (int node = wid; node < N_NODES; node += nw) {
        const float* xr = d_xa + (size_t)node * IN_F;
        float4 acc = __ldg((const float4*)b1 + lane);
        #pragma unroll
        for (int k = 0; k < IN_F; k++) {
            float v = __ldg(xr + k);
            float4 w = __ldg((const float4*)W1 + k * 32 + lane);
            acc.x += v * w.x; acc.y += v * w.y; acc.z += v * w.z; acc.w += v * w.w;
        }
        acc.x = fmaxf(acc.x, 0.f); acc.y = fmaxf(acc.y, 0.f);
        acc.z = fmaxf(acc.z, 0.f); acc.w = fmaxf(acc.w, 0.f);
        ((float4*)(d_h1 + (size_t)node * HID))[lane] = acc;
    }
    gbar();

    // ================== phase macros ==================
    // XFORM128: d_h0 = d_h1 @ W   (warp per 4 rows; W float4 reused x4)
    #define XFORM128(W)                                                      \
        for (int q = wid; q < N_NODES / 4; q += nw) {                        \
            const float* r0 = d_h1 + (size_t)(4 * q) * HID;                  \
            const float4* Wv = (const float4*)(W);                           \
            float4 a0 = make_float4(0.f,0.f,0.f,0.f), a1=a0, a2=a0, a3=a0;   \
            for (int k4 = 0; k4 < HID; k4 += 4) {                            \
                float4 x0 = *(const float4*)(r0 + k4);                       \
                float4 x1 = *(const float4*)(r0 + HID + k4);                 \
                float4 x2 = *(const float4*)(r0 + 2 * HID + k4);             \
                float4 x3 = *(const float4*)(r0 + 3 * HID + k4);             \
                float4 w;                                                    \
                w = __ldg(Wv + (k4 + 0) * 32 + lane);                        \
                a0.x+=x0.x*w.x; a0.y+=x0.x*w.y; a0.z+=x0.x*w.z; a0.w+=x0.x*w.w; \
                a1.x+=x1.x*w.x; a1.y+=x1.x*w.y; a1.z+=x1.x*w.z; a1.w+=x1.x*w.w; \
                a2.x+=x2.x*w.x; a2.y+=x2.x*w.y; a2.z+=x2.x*w.z; a2.w+=x2.x*w.w; \
                a3.x+=x3.x*w.x; a3.y+=x3.x*w.y; a3.z+=x3.x*w.z; a3.w+=x3.x*w.w; \
                w = __ldg(Wv + (k4 + 1) * 32 + lane);                        \
                a0.x+=x0.y*w.x; a0.y+=x0.y*w.y; a0.z+=x0.y*w.z; a0.w+=x0.y*w.w; \
                a1.x+=x1.y*w.x; a1.y+=x1.y*w.y; a1.z+=x1.y*w.z; a1.w+=x1.y*w.w; \
                a2.x+=x2.y*w.x; a2.y+=x2.y*w.y; a2.z+=x2.y*w.z; a2.w+=x2.y*w.w; \
                a3.x+=x3.y*w.x; a3.y+=x3.y*w.y; a3.z+=x3.y*w.z; a3.w+=x3.y*w.w; \
                w = __ldg(Wv + (k4 + 2) * 32 + lane);                        \
                a0.x+=x0.z*w.x; a0.y+=x0.z*w.y; a0.z+=x0.z*w.z; a0.w+=x0.z*w.w; \
                a1.x+=x1.z*w.x; a1.y+=x1.z*w.y; a1.z+=x1.z*w.z; a1.w+=x1.z*w.w; \
                a2.x+=x2.z*w.x; a2.y+=x2.z*w.y; a2.z+=x2.z*w.z; a2.w+=x2.z*w.w; \
                a3.x+=x3.z*w.x; a3.y+=x3.z*w.y; a3.z+=x3.z*w.z; a3.w+=x3.z*w.w; \
                w = __ldg(Wv + (k4 + 3) * 32 + lane);                        \
                a0.x+=x0.w*w.x; a0.y+=x0.w*w.y; a0.z+=x0.w*w.z; a0.w+=x0.w*w.w; \
                a1.x+=x1.w*w.x; a1.y+=x1.w*w.y; a1.z+=x1.w*w.z; a1.w+=x1.w*w.w; \
                a2.x+=x2.w*w.x; a2.y+=x2.w*w.y; a2.z+=x2.w*w.z; a2.w+=x2.w*w.w; \
                a3.x+=x3.w*w.x; a3.y+=x3.w*w.y; a3.z+=x3.w*w.z; a3.w+=x3.w*w.w; \
            }                                                                \
            float4* o = (float4*)(d_h0 + (size_t)(4 * q) * HID);             \
            o[lane] = a0; o[32 + lane] = a1;                                 \
            o[64 + lane] = a2; o[96 + lane] = a3;                            \
        }

    // GATHER: d_h1[n] = selfw*d_h0[n] + sum_in dis[s]*dis[n]*d_h0[s] + bias
    #define GATHER(BIAS, RELU)                                               \
        for (int node = wid; node < N_NODES; node += nw) {                   \
            float dv = d_dis[node];                                          \
            float4 h = ((const float4*)(d_h0 + (size_t)node * HID))[lane];   \
            float sw = dv * dv;                                              \
            float4 acc;                                                      \
            acc.x = sw * h.x; acc.y = sw * h.y;                              \
            acc.z = sw * h.z; acc.w = sw * h.w;                              \
            int st = d_rowptr[node];                                         \
            int cnt = d_deg[node] - 1;                                       \
            int sn = (cnt > 0) ? __ldg(d_csr_src + st) : 0;                  \
            for (int j = 0; j < cnt; j++) {                                  \
                int s = sn;                                                  \
                if (j + 1 < cnt) sn = __ldg(d_csr_src + st + j + 1);         \
                float w = __ldg(&d_dis[s]) * dv;                             \
                float4 v = ((const float4*)(d_h0 + (size_t)s * HID))[lane];  \
                acc.x += w * v.x; acc.y += w * v.y;                          \
                acc.z += w * v.z; acc.w += w * v.w;                          \
            }                                                                \
            float4 b = __ldg((const float4*)(BIAS) + lane);                  \
            acc.x += b.x; acc.y += b.y; acc.z += b.z; acc.w += b.w;          \
            if (RELU) {                                                      \
                acc.x = fmaxf(acc.x, 0.f); acc.y = fmaxf(acc.y, 0.f);        \
                acc.z = fmaxf(acc.z, 0.f); acc.w = fmaxf(acc.w, 0.f);        \
            }                                                                \
            ((float4*)(d_h1 + (size_t)node * HID))[lane] = acc;              \
        }

    // ---- P8-P9: layer 2 ----
    XFORM128(W2); gbar();
    GATHER(b2, 1); gbar();
    // ---- P10-P11: layer 3 (no relu) ----
    XFORM128(W3); gbar();
    GATHER(b3, 0); gbar();

    // ---- P12: mean-pool accumulate ----
    for (int i = gt; i < N_NODES * HID; i += NT) {
        int n = i >> 7, c = i & 127;
        int g = ld_idx(batch, n, bf);
        atomicAdd(&d_gsum[g * HID + c], d_h1[i]);
        if (c == 0) atomicAdd(&d_gcnt[g], 1);
    }
    gbar();

    // ---- P13: head ----
    for (int i = gt; i < N_GRAPHS * OUT_F; i += NT) {
        int g = i / OUT_F, c = i - g * OUT_F;
        float inv = 1.f / (float)max(d_gcnt[g], 1);
        float acc = __ldg(bl + c);
        #pragma unroll 8
        for (int k = 0; k < HID; k++)
            acc += (d_gsum[g * HID + k] * inv) * __ldg(Wl + k * OUT_F + c);
        out[i] = acc;
    }
}

// ---------------- launch ---------------------------------------------------------
extern "C" void kernel_launch(void* const* d_in, const int* in_sizes, int n_in,
                              void* d_out, int out_size) {
    const float *x = 0, *W1 = 0, *W2 = 0, *W3 = 0, *Wl = 0, *bl = 0;
    const float *bias[3] = {0, 0, 0};
    const int *ei = 0, *batch = 0;
    int nbias = 0, nW = 0;
    for (int i = 0; i < n_in; i++) {
        int sz = in_sizes[i];
        const void* p = d_in[i];
        switch (sz) {
            case N_NODES * IN_F:   x     = (const float*)p;  break;
            case 2 * N_EDGES:      ei    = (const int*)p;    break;
            case N_NODES:          batch = (const int*)p;    break;
            case IN_F * HID:       W1    = (const float*)p;  break;
            case HID * HID:        if (nW == 0) W2 = (const float*)p; else W3 = (const float*)p; nW++; break;
            case HID:              if (nbias < 3) bias[nbias++] = (const float*)p; break;
            case HID * OUT_F:      Wl    = (const float*)p;  break;
            case OUT_F:            bl    = (const float*)p;  break;
            default: break;
        }
    }

    int sm = 148, mb = 1;
    cudaDeviceGetAttribute(&sm, cudaDevAttrMultiProcessorCount, 0);
    cudaOccupancyMaxActiveBlocksPerMultiprocessor(&mb, k_uber, NTHR, 0);
    if (mb < 1) mb = 1;
    if (mb > 4) mb = 4;
    int grid = sm * mb;

    k_uber<<<grid, NTHR>>>(x, ei, batch,
                           W1, bias[0], W2, bias[1], W3, bias[2],
                           Wl, bl, (float*)d_out);
}

// round 14
// speedup vs baseline: 17.6740x; 1.0418x over previous
#include <cuda_runtime.h>

#define N_NODES  100000
#define N_EDGES  1600000
#define HID      128
#define IN_F     10
#define OUT_F    101
#define N_GRAPHS 64
#define NTHR     256
#define NSC      ((N_NODES + NTHR - 1) / NTHR)   // 391 scan blocks

// ---------------- device state (single-launch lifetime) ------------------------
__device__ __align__(16) float d_h0[(size_t)N_NODES * HID];
__device__ __align__(16) float d_h1[(size_t)N_NODES * HID];
__device__ int   d_deg[N_NODES];
__device__ float d_dis[N_NODES];
__device__ int   d_rowptr[N_NODES];
__device__ int   d_cursor[N_NODES];
__device__ int   d_bsum[NSC];
__device__ int   d_csr_src[N_EDGES];
__device__ float d_gsum[N_GRAPHS * HID];
__device__ int   d_gcnt[N_GRAPHS];
__device__ int   d_ei64, d_b64;
__device__ int   g_arrive;            // monotonic grid-barrier ticket

__device__ __forceinline__ int ld_idx(const int* __restrict__ p, int i, int is64) {
    return is64 ? __ldg(p + 2 * (size_t)i) : __ldg(p + i);
}

// packed fp32x2 FMA (full-rate fp32 on sm_103a; plain FFMA is half-rate)
#define FFMA2(acc, a, b) \
    asm("fma.rn.f32x2 %0, %1, %2, %0;" : "+l"(acc) : "l"(a), "l"(b))
#define PACKVV(out, v) \
    asm("mov.b64 %0, {%1, %1};" : "=l"(out) : "r"(__float_as_uint(v)))

// Grid barrier (proven R11-R13): co-resident grid, monotonic ticket, fences.
__device__ __forceinline__ void gbar() {
    __threadfence();
    __syncthreads();
    if (threadIdx.x == 0) {
        int g = gridDim.x;
        int t = atomicAdd(&g_arrive, 1);
        int target = (t / g + 1) * g;
        while (*((volatile int*)&g_arrive) < target) __nanosleep(64);
    }
    __syncthreads();
    __threadfence();
}

// ---------------- XFORM: d_h0 = d_h1 @ W (warp per 4 rows, f32x2 packed) ------
__device__ __forceinline__ void xform128(const float* __restrict__ W,
                                         int wid, int nw, int lane) {
    for (int q = wid; q < N_NODES / 4; q += nw) {
        const float* r = d_h1 + (size_t)(4 * q) * HID;
        unsigned long long a01[4] = {0ull, 0ull, 0ull, 0ull};
        unsigned long long a23[4] = {0ull, 0ull, 0ull, 0ull};
        #pragma unroll 2
        for (int k4 = 0; k4 < HID; k4 += 4) {
            float4 xr[4];
            #pragma unroll
            for (int t = 0; t < 4; t++)
                xr[t] = *(const float4*)(r + t * HID + k4);
            #pragma unroll
            for (int kk = 0; kk < 4; kk++) {
                double2 wp = __ldg((const double2*)(W + (size_t)(k4 + kk) * HID) + lane);
                unsigned long long w01 = (unsigned long long)__double_as_longlong(wp.x);
                unsigned long long w23 = (unsigned long long)__double_as_longlong(wp.y);
                #pragma unroll
                for (int t = 0; t < 4; t++) {
                    float v = (kk == 0) ? xr[t].x : (kk == 1) ? xr[t].y
                             : (kk == 2) ? xr[t].z : xr[t].w;
                    unsigned long long vv;
                    PACKVV(vv, v);
                    FFMA2(a01[t], w01, vv);
                    FFMA2(a23[t], w23, vv);
                }
            }
        }
        #pragma unroll
        for (int t = 0; t < 4; t++) {
            double2 st;
            st.x = __longlong_as_double((long long)a01[t]);
            st.y = __longlong_as_double((long long)a23[t]);
            ((double2*)(d_h0 + (size_t)(4 * q + t) * HID))[lane] = st;
        }
    }
}

// ---------------- GATHER: d_h1 = A_norm*d_h0 + bias (optional relu) -----------
__device__ __forceinline__ void gather128(const float* __restrict__ bias, int relu,
                                          int wid, int nw, int lane) {
    for (int node = wid; node < N_NODES; node += nw) {
        float dv = d_dis[node];
        float4 h = ((const float4*)(d_h0 + (size_t)node * HID))[lane];
        float sw = dv * dv;
        float4 acc;
        acc.x = sw * h.x; acc.y = sw * h.y; acc.z = sw * h.z; acc.w = sw * h.w;
        int st = d_rowptr[node];
        int cnt = d_deg[node] - 1;
        int sn = (cnt > 0) ? __ldg(d_csr_src + st) : 0;
        for (int j = 0; j < cnt; j++) {
            int s = sn;
            if (j + 1 < cnt) sn = __ldg(d_csr_src + st + j + 1);
            float w = __ldg(&d_dis[s]) * dv;
            float4 v = ((const float4*)(d_h0 + (size_t)s * HID))[lane];
            acc.x += w * v.x; acc.y += w * v.y;
            acc.z += w * v.z; acc.w += w * v.w;
        }
        float4 b = __ldg((const float4*)bias + lane);
        acc.x += b.x; acc.y += b.y; acc.z += b.z; acc.w += b.w;
        if (relu) {
            acc.x = fmaxf(acc.x, 0.f); acc.y = fmaxf(acc.y, 0.f);
            acc.z = fmaxf(acc.z, 0.f); acc.w = fmaxf(acc.w, 0.f);
        }
        ((float4*)(d_h1 + (size_t)node * HID))[lane] = acc;
    }
}

__global__ void __launch_bounds__(NTHR, 4)
k_uber(const float* __restrict__ x, const int* __restrict__ ei,
       const int* __restrict__ batch,
       const float* __restrict__ W1, const float* __restrict__ b1,
       const float* __restrict__ W2, const float* __restrict__ b2,
       const float* __restrict__ W3, const float* __restrict__ b3,
       const float* __restrict__ Wl, const float* __restrict__ bl,
       float* __restrict__ out) {
    const int NT   = gridDim.x * blockDim.x;
    const int gt   = blockIdx.x * blockDim.x + threadIdx.x;
    const int lane = threadIdx.x & 31;
    const int wid  = gt >> 5;
    const int nw   = NT >> 5;
    __shared__ int sh[512];

    // ---- P0: init + dtype detection ----
    for (int i = gt; i < N_NODES; i += NT) d_deg[i] = 1;        // self-loop
    for (int i = gt; i < N_GRAPHS * HID; i += NT) d_gsum[i] = 0.f;
    for (int i = gt; i < N_GRAPHS; i += NT) d_gcnt[i] = 0;
    if (blockIdx.x == 0) {
        __shared__ int s_ei, s_b;
        if (threadIdx.x == 0) { s_ei = 1; s_b = 1; }
        __syncthreads();
        for (int k = 0; k < 8; k++) {
            int t = threadIdx.x * 8 + k;
            if (__ldg(ei + ((t * (2 * N_EDGES / 2048)) | 1)) != 0) s_ei = 0;
            if (__ldg(batch + ((t * (N_NODES / 2048)) | 1)) != 0) s_b = 0;
        }
        __syncthreads();
        if (threadIdx.x == 0) { d_ei64 = s_ei; d_b64 = s_b; }
    }
    gbar();
    const int ef = d_ei64;
    const int bf = d_b64;

    // ---- P1: degree histogram ----
    for (int e = gt; e < N_EDGES; e += NT)
        atomicAdd(&d_deg[ld_idx(ei, N_EDGES + e, ef)], 1);
    gbar();

    // ---- P2: dis = rsqrt(deg) + scan phase A ----
    for (int i = gt; i < N_NODES; i += NT)
        d_dis[i] = rsqrtf((float)d_deg[i]);
    if (blockIdx.x < NSC) {
        int i = blockIdx.x * NTHR + threadIdx.x;
        int c = (i < N_NODES) ? (d_deg[i] - 1) : 0;
        sh[threadIdx.x] = c;
        __syncthreads();
        #pragma unroll
        for (int off = 1; off < NTHR; off <<= 1) {
            int t = (threadIdx.x >= off) ? sh[threadIdx.x - off] : 0;
            __syncthreads();
            sh[threadIdx.x] += t;
            __syncthreads();
        }
        if (i < N_NODES) d_rowptr[i] = sh[threadIdx.x] - c;
        if (threadIdx.x == NTHR - 1) d_bsum[blockIdx.x] = sh[NTHR - 1];
    }
    gbar();

    // ---- P3: scan phase B ----
    if (blockIdx.x == 0) {
        for (int t = threadIdx.x; t < NSC; t += NTHR) sh[t] = d_bsum[t];
        __syncthreads();
        if (threadIdx.x == 0) {
            int run = 0;
            for (int b = 0; b < NSC; b++) { int t = sh[b]; sh[b] = run; run += t; }
        }
        __syncthreads();
        for (int t = threadIdx.x; t < NSC; t += NTHR) d_bsum[t] = sh[t];
    }
    gbar();

    // ---- P4: scan phase C ----
    for (int i = gt; i < N_NODES; i += NT) {
        int v = d_rowptr[i] + d_bsum[i / NTHR];
        d_rowptr[i] = v;
        d_cursor[i] = v;
    }
    gbar();

    // ---- P5: CSR fill ----
    for (int e = gt; e < N_EDGES; e += NT) {
        int s = ld_idx(ei, e, ef);
        int d = ld_idx(ei, N_EDGES + e, ef);
        d_csr_src[atomicAdd(&d_cursor[d], 1)] = s;
    }
    gbar();

    // ---- P6: fused xa-gather + layer-1 transform (warp per node) ----
    // xa[k] (k<10) in lane k's register; then h1 = relu(xa @ W1 + b1).
    for (int node = wid; node < N_NODES; node += nw) {
        float dv = d_dis[node];
        float a = 0.f;
        if (lane < IN_F)
            a = dv * dv * __ldg(x + (size_t)node * IN_F + lane);
        int st = d_rowptr[node], cnt = d_deg[node] - 1;
        for (int j = 0; j < cnt; j++) {
            int s = __ldg(d_csr_src + st + j);
            float w = __ldg(&d_dis[s]) * dv;
            if (lane < IN_F)
                a += w * __ldg(x + (size_t)s * IN_F + lane);
        }
        float4 acc = __ldg((const float4*)b1 + lane);
        #pragma unroll
        for (int k = 0; k < IN_F; k++) {
            float v = __shfl_sync(0xffffffffu, a, k);
            float4 w = __ldg((const float4*)W1 + k * 32 + lane);
            acc.x += v * w.x; acc.y += v * w.y;
            acc.z += v * w.z; acc.w += v * w.w;
        }
        acc.x = fmaxf(acc.x, 0.f); acc.y = fmaxf(acc.y, 0.f);
        acc.z = fmaxf(acc.z, 0.f); acc.w = fmaxf(acc.w, 0.f);
        ((float4*)(d_h1 + (size_t)node * HID))[lane] = acc;
    }
    gbar();

    // ---- P7-P8: layer 2 ----
    xform128(W2, wid, nw, lane); gbar();
    gather128(b2, 1, wid, nw, lane); gbar();
    // ---- P9-P10: layer 3 (no relu) ----
    xform128(W3, wid, nw, lane); gbar();
    gather128(b3, 0, wid, nw, lane); gbar();

    // ---- P11: segmented mean-pool (batch sorted => few flushes) ----
    {
        int per = (N_NODES + nw - 1) / nw;
        int n0 = wid * per;
        int n1 = (n0 + per < N_NODES) ? n0 + per : N_NODES;
        if (n0 < n1) {
            float4 acc = make_float4(0.f, 0.f, 0.f, 0.f);
            int cnt = 0;
            int curg = ld_idx(batch, n0, bf);
            for (int n = n0; n < n1; n++) {
                int g = ld_idx(batch, n, bf);
                if (g != curg) {
                    float* base = d_gsum + curg * HID + lane * 4;
                    atomicAdd(base + 0, acc.x); atomicAdd(base + 1, acc.y);
                    atomicAdd(base + 2, acc.z); atomicAdd(base + 3, acc.w);
                    if (lane == 0) atomicAdd(&d_gcnt[curg], cnt);
                    acc = make_float4(0.f, 0.f, 0.f, 0.f);
                    cnt = 0;
                    curg = g;
                }
                float4 v = ((const float4*)(d_h1 + (size_t)n * HID))[lane];
                acc.x += v.x; acc.y += v.y; acc.z += v.z; acc.w += v.w;
                cnt++;
            }
            float* base = d_gsum + curg * HID + lane * 4;
            atomicAdd(base + 0, acc.x); atomicAdd(base + 1, acc.y);
            atomicAdd(base + 2, acc.z); atomicAdd(base + 3, acc.w);
            if (lane == 0) atomicAdd(&d_gcnt[curg], cnt);
        }
    }
    gbar();

    // ---- P12: head ----
    for (int i = gt; i < N_GRAPHS * OUT_F; i += NT) {
        int g = i / OUT_F, c = i - g * OUT_F;
        float inv = 1.f / (float)max(d_gcnt[g], 1);
        float acc = __ldg(bl + c);
        #pragma unroll 8
        for (int k = 0; k < HID; k++)
            acc += (d_gsum[g * HID + k] * inv) * __ldg(Wl + k * OUT_F + c);
        out[i] = acc;
    }
}

// ---------------- launch ---------------------------------------------------------
extern "C" void kernel_launch(void* const* d_in, const int* in_sizes, int n_in,
                              void* d_out, int out_size) {
    const float *x = 0, *W1 = 0, *W2 = 0, *W3 = 0, *Wl = 0, *bl = 0;
    const float *bias[3] = {0, 0, 0};
    const int *ei = 0, *batch = 0;
    int nbias = 0, nW = 0;
    for (int i = 0; i < n_in; i++) {
        int sz = in_sizes[i];
        const void* p = d_in[i];
        switch (sz) {
            case N_NODES * IN_F:   x     = (const float*)p;  break;
            case 2 * N_EDGES:      ei    = (const int*)p;    break;
            case N_NODES:          batch = (const int*)p;    break;
            case IN_F * HID:       W1    = (const float*)p;  break;
            case HID * HID:        if (nW == 0) W2 = (const float*)p; else W3 = (const float*)p; nW++; break;
            case HID:              if (nbias < 3) bias[nbias++] = (const float*)p; break;
            case HID * OUT_F:      Wl    = (const float*)p;  break;
            case OUT_F:            bl    = (const float*)p;  break;
            default: break;
        }
    }

    int sm = 148, mb = 1;
    cudaDeviceGetAttribute(&sm, cudaDevAttrMultiProcessorCount, 0);
    cudaOccupancyMaxActiveBlocksPerMultiprocessor(&mb, k_uber, NTHR, 0);
    if (mb < 1) mb = 1;
    if (mb > 4) mb = 4;
    int grid = sm * mb;

    k_uber<<<grid, NTHR>>>(x, ei, batch,
                           W1, bias[0], W2, bias[1], W3, bias[2],
                           Wl, bl, (float*)d_out);
}